// round 2
// baseline (speedup 1.0000x reference)
#include <cuda_runtime.h>
#include <math.h>
#include <stdint.h>

#define BB 8
#define TT 2048
#define SS 2048
#define DD 256
#define NCHUNK 16
#define TCH 128   /* TT / NCHUNK */

// ---------------- scratch (device globals; no runtime allocation) ----------------
__device__ float        g_align [(size_t)BB * TT * SS]; // logits, then exp_score in place (134MB)
__device__ unsigned int g_rowmax[BB * TT];              // monotone-uint encoded row max
__device__ float        g_carry [BB * NCHUNK * SS];     // per-chunk column sums -> exclusive prefix
__device__ float        g_partial[(size_t)BB * TT * 64];// per (row, sblk*8+warp) partial rowsums
__device__ float        g_rowsum[BB * TT];
__device__ float        g_c     [(size_t)BB * TT * DD]; // context vectors (16MB)

// ---------------- helpers ----------------
__device__ __forceinline__ void ffma2(unsigned long long& d, unsigned long long a, unsigned long long b) {
    asm("fma.rn.f32x2 %0, %1, %2, %0;" : "+l"(d) : "l"(a), "l"(b));
}
__device__ __forceinline__ unsigned long long fdup(float x) {
    unsigned long long r;
    asm("mov.b64 %0, {%1, %1};" : "=l"(r) : "f"(x));
    return r;
}
__device__ __forceinline__ float lo32(unsigned long long v) { return __uint_as_float((unsigned)(v & 0xffffffffull)); }
__device__ __forceinline__ float hi32(unsigned long long v) { return __uint_as_float((unsigned)(v >> 32)); }

// monotone map float -> uint so atomicMax works (handles negatives & -inf)
__device__ __forceinline__ unsigned fenc(float f) {
    unsigned u = __float_as_uint(f);
    return (u & 0x80000000u) ? ~u : (u | 0x80000000u);
}
__device__ __forceinline__ float fdec(unsigned e) {
    return (e & 0x80000000u) ? __uint_as_float(e ^ 0x80000000u) : __uint_as_float(~e);
}

// dtype-robust length decode: jax default config silently makes int64 -> int32.
// Lengths are in [1, S], so an int64 buffer viewed as int32 has zero high words
// at odd indices; a genuine int32 buffer has nonzero (>=1) values there.
__device__ __forceinline__ int decode_len(const int* __restrict__ lens32, int b) {
    bool is64 = (lens32[1] == 0) && (lens32[3] == 0) && (lens32[5] == 0) && (lens32[7] == 0);
    if (is64) return (int)((const long long*)lens32)[b];
    return lens32[b];
}

// ---------------- init ----------------
__global__ void k_init() {
    int i = blockIdx.x * blockDim.x + threadIdx.x;
    if (i < BB * TT) g_rowmax[i] = 0x007FFFFFu;  // fenc(-inf)
}

// ---------------- GEMM1: align = source @ memory_bank^T, mask, rowmax ----------------
__global__ void __launch_bounds__(256) k_gemm1(const float* __restrict__ src,
                                               const float* __restrict__ mb,
                                               const int* __restrict__ lens32) {
    __shared__ __align__(16) unsigned long long As2[16][132]; // dup-packed A (t-major transposed)
    __shared__ __align__(16) float              Bs [16][132]; // B (s-major transposed)
    __shared__ float red[128][16];

    const int tid = threadIdx.x;
    const int tx = tid & 15, ty = tid >> 4;
    const int bz = blockIdx.z;
    const int t0 = blockIdx.y * 128;
    const int s0 = blockIdx.x * 128;

    const float* A  = src + (size_t)bz * TT * DD;
    const float* Bm = mb  + (size_t)bz * SS * DD;

    unsigned long long acc[8][4];
#pragma unroll
    for (int i = 0; i < 8; ++i)
#pragma unroll
        for (int j = 0; j < 4; ++j) acc[i][j] = 0ull;

    for (int k0 = 0; k0 < DD; k0 += 16) {
#pragma unroll
        for (int l = 0; l < 2; ++l) {
            int idx = tid + l * 256;
            int row = idx >> 2, c4 = idx & 3;
            float4 va = *(const float4*)(A  + (size_t)(t0 + row) * DD + k0 + c4 * 4);
            As2[c4 * 4 + 0][row] = fdup(va.x);
            As2[c4 * 4 + 1][row] = fdup(va.y);
            As2[c4 * 4 + 2][row] = fdup(va.z);
            As2[c4 * 4 + 3][row] = fdup(va.w);
            float4 vb = *(const float4*)(Bm + (size_t)(s0 + row) * DD + k0 + c4 * 4);
            Bs[c4 * 4 + 0][row] = vb.x;
            Bs[c4 * 4 + 1][row] = vb.y;
            Bs[c4 * 4 + 2][row] = vb.z;
            Bs[c4 * 4 + 3][row] = vb.w;
        }
        __syncthreads();
#pragma unroll
        for (int k = 0; k < 16; ++k) {
            const ulonglong2* ap = (const ulonglong2*)&As2[k][ty * 8];
            ulonglong2 a01 = ap[0], a23 = ap[1], a45 = ap[2], a67 = ap[3];
            unsigned long long a[8] = {a01.x, a01.y, a23.x, a23.y, a45.x, a45.y, a67.x, a67.y};
            const unsigned long long* bp = (const unsigned long long*)&Bs[k][tx * 8];
            unsigned long long b0 = bp[0], b1 = bp[1], b2 = bp[2], b3 = bp[3];
#pragma unroll
            for (int i = 0; i < 8; ++i) {
                ffma2(acc[i][0], a[i], b0);
                ffma2(acc[i][1], a[i], b1);
                ffma2(acc[i][2], a[i], b2);
                ffma2(acc[i][3], a[i], b3);
            }
        }
        __syncthreads();
    }

    const int len = decode_len(lens32, bz);
#pragma unroll
    for (int i = 0; i < 8; ++i) {
        int t  = t0 + ty * 8 + i;
        int sb = s0 + tx * 8;
        float v[8];
#pragma unroll
        for (int j = 0; j < 4; ++j) { v[2 * j] = lo32(acc[i][j]); v[2 * j + 1] = hi32(acc[i][j]); }
        float m = -INFINITY;
#pragma unroll
        for (int jj = 0; jj < 8; ++jj) {
            if (sb + jj >= len) v[jj] = -INFINITY;
            m = fmaxf(m, v[jj]);
        }
        float4* op = (float4*)(g_align + (size_t)(bz * TT + t) * SS + sb);
        op[0] = make_float4(v[0], v[1], v[2], v[3]);
        op[1] = make_float4(v[4], v[5], v[6], v[7]);
        red[ty * 8 + i][tx] = m;
    }
    __syncthreads();
    if (tid < 128) {
        float m = red[tid][0];
#pragma unroll
        for (int j = 1; j < 16; ++j) m = fmaxf(m, red[tid][j]);
        atomicMax(&g_rowmax[bz * TT + t0 + tid], fenc(m));
    }
}

// ---------------- Phase A: exp in place + per-chunk column sums ----------------
__global__ void __launch_bounds__(256) k_colsum() {
    const int b  = blockIdx.z;
    const int ch = blockIdx.y;
    const int s  = blockIdx.x * 256 + threadIdx.x;
    __shared__ float mrow[TCH];
    if (threadIdx.x < TCH) mrow[threadIdx.x] = fdec(g_rowmax[b * TT + ch * TCH + threadIdx.x]);
    __syncthreads();
    size_t base = (size_t)(b * TT + ch * TCH) * SS + s;
    float sum = 0.f;
#pragma unroll 4
    for (int r = 0; r < TCH; ++r) {
        size_t off = base + (size_t)r * SS;
        float e = expf(g_align[off] - mrow[r]);
        g_align[off] = e;
        sum += e;
    }
    g_carry[(b * NCHUNK + ch) * SS + s] = sum;
}

// ---------------- tiny exclusive scan over chunks ----------------
__global__ void k_scan() {
    int i = blockIdx.x * blockDim.x + threadIdx.x;
    if (i >= BB * SS) return;
    int b = i / SS, s = i % SS;
    float run = 0.f;
    for (int c = 0; c < NCHUNK; ++c) {
        int idx = (b * NCHUNK + c) * SS + s;
        float v = g_carry[idx];
        g_carry[idx] = run;
        run += v;
    }
}

// ---------------- Phase C: penalty replay, unnormalized weights, partial rowsums ----------------
__global__ void __launch_bounds__(256) k_phasec(float* __restrict__ av) {
    const int b  = blockIdx.z;
    const int ch = blockIdx.y;
    const int s  = blockIdx.x * 256 + threadIdx.x;
    const int lane = threadIdx.x & 31;
    const int warp = threadIdx.x >> 5;

    float P = g_carry[(b * NCHUNK + ch) * SS + s];
    size_t base = (size_t)(b * TT + ch * TCH) * SS + s;
    for (int r = 0; r < TCH; ++r) {
        int t = ch * TCH + r;
        size_t off = base + (size_t)r * SS;
        float e = g_align[off];
        float pen = (t == 0) ? 1.0f : P;
        float u = e / (pen + 1e-20f);
        P += e;
        av[off] = u;
        float w = u;
        w += __shfl_down_sync(0xffffffffu, w, 16);
        w += __shfl_down_sync(0xffffffffu, w, 8);
        w += __shfl_down_sync(0xffffffffu, w, 4);
        w += __shfl_down_sync(0xffffffffu, w, 2);
        w += __shfl_down_sync(0xffffffffu, w, 1);
        if (lane == 0) g_partial[(size_t)(b * TT + t) * 64 + blockIdx.x * 8 + warp] = w;
    }
}

// ---------------- deterministic rowsum reduce ----------------
__global__ void k_rowsum() {
    int i = blockIdx.x * blockDim.x + threadIdx.x;
    if (i >= BB * TT) return;
    const float* p = g_partial + (size_t)i * 64;
    float s = 0.f;
#pragma unroll
    for (int j = 0; j < 64; ++j) s += p[j];
    g_rowsum[i] = s;
}

// ---------------- normalize align_vectors in place ----------------
__global__ void __launch_bounds__(256) k_norm(float* __restrict__ av) {
    int row = blockIdx.x;
    float inv = 1.0f / g_rowsum[row];
    float4* p = (float4*)(av + (size_t)row * SS);
    int t = threadIdx.x;
    float4 a = p[t];
    a.x *= inv; a.y *= inv; a.z *= inv; a.w *= inv;
    p[t] = a;
    float4 c = p[t + 256];
    c.x *= inv; c.y *= inv; c.z *= inv; c.w *= inv;
    p[t + 256] = c;
}

// ---------------- GEMM2: c = align_vectors @ memory_bank ----------------
__global__ void __launch_bounds__(256) k_gemm2(const float* __restrict__ avn,
                                               const float* __restrict__ mb) {
    __shared__ __align__(16) unsigned long long As2[16][132];
    __shared__ __align__(16) float              Bs [16][132];

    const int tid = threadIdx.x;
    const int tx = tid & 15, ty = tid >> 4;
    const int bz = blockIdx.z;
    const int t0 = blockIdx.y * 128;
    const int n0 = blockIdx.x * 128;

    const float* A  = avn + (size_t)bz * TT * SS;
    const float* Bm = mb  + (size_t)bz * SS * DD;

    unsigned long long acc[8][4];
#pragma unroll
    for (int i = 0; i < 8; ++i)
#pragma unroll
        for (int j = 0; j < 4; ++j) acc[i][j] = 0ull;

    for (int k0 = 0; k0 < SS; k0 += 16) {
#pragma unroll
        for (int l = 0; l < 2; ++l) {
            int idx = tid + l * 256;
            int row = idx >> 2, c4 = idx & 3;
            float4 va = *(const float4*)(A + (size_t)(t0 + row) * SS + k0 + c4 * 4);
            As2[c4 * 4 + 0][row] = fdup(va.x);
            As2[c4 * 4 + 1][row] = fdup(va.y);
            As2[c4 * 4 + 2][row] = fdup(va.z);
            As2[c4 * 4 + 3][row] = fdup(va.w);
            int r2 = idx >> 5, c2 = (idx & 31) * 4;
            float4 vb = *(const float4*)(Bm + (size_t)(k0 + r2) * DD + n0 + c2);
            *(float4*)&Bs[r2][c2] = vb;
        }
        __syncthreads();
#pragma unroll
        for (int k = 0; k < 16; ++k) {
            const ulonglong2* ap = (const ulonglong2*)&As2[k][ty * 8];
            ulonglong2 a01 = ap[0], a23 = ap[1], a45 = ap[2], a67 = ap[3];
            unsigned long long a[8] = {a01.x, a01.y, a23.x, a23.y, a45.x, a45.y, a67.x, a67.y};
            const unsigned long long* bp = (const unsigned long long*)&Bs[k][tx * 8];
            unsigned long long b0 = bp[0], b1 = bp[1], b2 = bp[2], b3 = bp[3];
#pragma unroll
            for (int i = 0; i < 8; ++i) {
                ffma2(acc[i][0], a[i], b0);
                ffma2(acc[i][1], a[i], b1);
                ffma2(acc[i][2], a[i], b2);
                ffma2(acc[i][3], a[i], b3);
            }
        }
        __syncthreads();
    }

#pragma unroll
    for (int i = 0; i < 8; ++i) {
        int t = t0 + ty * 8 + i;
        float v[8];
#pragma unroll
        for (int j = 0; j < 4; ++j) { v[2 * j] = lo32(acc[i][j]); v[2 * j + 1] = hi32(acc[i][j]); }
        float4* op = (float4*)(g_c + (size_t)(bz * TT + t) * DD + n0 + tx * 8);
        op[0] = make_float4(v[0], v[1], v[2], v[3]);
        op[1] = make_float4(v[4], v[5], v[6], v[7]);
    }
}

// ---------------- GEMM3: attn_h = tanh([c, source] @ W_out) ----------------
__global__ void __launch_bounds__(256) k_gemm3(const float* __restrict__ src,
                                               const float* __restrict__ W,
                                               float* __restrict__ outh) {
    __shared__ __align__(16) unsigned long long As2[16][132];
    __shared__ __align__(16) float              Bs [16][132];

    const int tid = threadIdx.x;
    const int tx = tid & 15, ty = tid >> 4;
    const int m0 = blockIdx.y * 128;
    const int n0 = blockIdx.x * 128;

    unsigned long long acc[8][4];
#pragma unroll
    for (int i = 0; i < 8; ++i)
#pragma unroll
        for (int j = 0; j < 4; ++j) acc[i][j] = 0ull;

    for (int k0 = 0; k0 < 2 * DD; k0 += 16) {
#pragma unroll
        for (int l = 0; l < 2; ++l) {
            int idx = tid + l * 256;
            int row = idx >> 2, c4 = idx & 3;
            int m = m0 + row;
            int kg = k0 + c4 * 4;
            const float* ap = (kg < DD) ? (g_c + (size_t)m * DD + kg)
                                        : (src + (size_t)m * DD + (kg - DD));
            float4 va = *(const float4*)ap;
            As2[c4 * 4 + 0][row] = fdup(va.x);
            As2[c4 * 4 + 1][row] = fdup(va.y);
            As2[c4 * 4 + 2][row] = fdup(va.z);
            As2[c4 * 4 + 3][row] = fdup(va.w);
            int r2 = idx >> 5, c2 = (idx & 31) * 4;
            float4 vb = *(const float4*)(W + (size_t)(k0 + r2) * DD + n0 + c2);
            *(float4*)&Bs[r2][c2] = vb;
        }
        __syncthreads();
#pragma unroll
        for (int k = 0; k < 16; ++k) {
            const ulonglong2* ap = (const ulonglong2*)&As2[k][ty * 8];
            ulonglong2 a01 = ap[0], a23 = ap[1], a45 = ap[2], a67 = ap[3];
            unsigned long long a[8] = {a01.x, a01.y, a23.x, a23.y, a45.x, a45.y, a67.x, a67.y};
            const unsigned long long* bp = (const unsigned long long*)&Bs[k][tx * 8];
            unsigned long long b0 = bp[0], b1 = bp[1], b2 = bp[2], b3 = bp[3];
#pragma unroll
            for (int i = 0; i < 8; ++i) {
                ffma2(acc[i][0], a[i], b0);
                ffma2(acc[i][1], a[i], b1);
                ffma2(acc[i][2], a[i], b2);
                ffma2(acc[i][3], a[i], b3);
            }
        }
        __syncthreads();
    }

#pragma unroll
    for (int i = 0; i < 8; ++i) {
        int m = m0 + ty * 8 + i;
        float v[8];
#pragma unroll
        for (int j = 0; j < 4; ++j) { v[2 * j] = lo32(acc[i][j]); v[2 * j + 1] = hi32(acc[i][j]); }
#pragma unroll
        for (int jj = 0; jj < 8; ++jj) v[jj] = tanhf(v[jj]);
        float4* op = (float4*)(outh + (size_t)m * DD + n0 + tx * 8);
        op[0] = make_float4(v[0], v[1], v[2], v[3]);
        op[1] = make_float4(v[4], v[5], v[6], v[7]);
    }
}

// ---------------- launch ----------------
extern "C" void kernel_launch(void* const* d_in, const int* in_sizes, int n_in,
                              void* d_out, int out_size) {
    const float* src  = (const float*)d_in[0];      // [B,T,D]
    const float* mb   = (const float*)d_in[1];      // [B,S,D]
    const float* W    = (const float*)d_in[2];      // [2D,D]
    const int*   lens = (const int*)d_in[3];        // [B] int32 or int64 (decoded in-kernel)

    float* outh = (float*)d_out;                    // attn_h   [B,T,D]
    float* av   = outh + (size_t)BB * TT * DD;      // align_vectors [B,T,S]

    k_init<<<(BB * TT + 255) / 256, 256>>>();
    k_gemm1<<<dim3(SS / 128, TT / 128, BB), 256>>>(src, mb, lens);
    k_colsum<<<dim3(SS / 256, NCHUNK, BB), 256>>>();
    k_scan<<<(BB * SS + 255) / 256, 256>>>();
    k_phasec<<<dim3(SS / 256, NCHUNK, BB), 256>>>(av);
    k_rowsum<<<(BB * TT + 255) / 256, 256>>>();
    k_norm<<<BB * TT, 256>>>(av);
    k_gemm2<<<dim3(DD / 128, TT / 128, BB), 256>>>(av, mb);
    k_gemm3<<<dim3(DD / 128, (BB * TT) / 128, 1), 256>>>(src, W, outh);
}

// round 3
// speedup vs baseline: 1.2836x; 1.2836x over previous
#include <cuda_runtime.h>
#include <math.h>
#include <stdint.h>

#define BB 8
#define TT 2048
#define SS 2048
#define DD 256
#define NCHUNK 16
#define TCH 128   /* TT / NCHUNK */

// ---------------- scratch (device globals; no runtime allocation) ----------------
__device__ float        g_align [(size_t)BB * TT * SS]; // logits, then unnormalized u in place
__device__ unsigned int g_rowmax[BB * TT];              // monotone-uint encoded row max
__device__ float        g_carry [BB * NCHUNK * SS];     // per-chunk column sums -> exclusive prefix
__device__ float        g_partial[(size_t)BB * TT * 64];// per (row, sblk*8+warp) partial rowsums
__device__ float        g_invsum[BB * TT];              // 1 / rowsum
__device__ float        g_c     [(size_t)BB * TT * DD]; // context vectors (16MB)

// ---------------- helpers ----------------
__device__ __forceinline__ void ffma2(unsigned long long& d, unsigned long long a, unsigned long long b) {
    asm("fma.rn.f32x2 %0, %1, %2, %0;" : "+l"(d) : "l"(a), "l"(b));
}
__device__ __forceinline__ unsigned long long fdup(float x) {
    unsigned long long r;
    asm("mov.b64 %0, {%1, %1};" : "=l"(r) : "f"(x));
    return r;
}
__device__ __forceinline__ float lo32(unsigned long long v) { return __uint_as_float((unsigned)(v & 0xffffffffull)); }
__device__ __forceinline__ float hi32(unsigned long long v) { return __uint_as_float((unsigned)(v >> 32)); }

__device__ __forceinline__ unsigned fenc(float f) {
    unsigned u = __float_as_uint(f);
    return (u & 0x80000000u) ? ~u : (u | 0x80000000u);
}
__device__ __forceinline__ float fdec(unsigned e) {
    return (e & 0x80000000u) ? __uint_as_float(e ^ 0x80000000u) : __uint_as_float(~e);
}

// dtype-robust length decode (jax may hand us int32 despite int64 in reference)
__device__ __forceinline__ int decode_len(const int* __restrict__ lens32, int b) {
    bool is64 = (lens32[1] == 0) && (lens32[3] == 0) && (lens32[5] == 0) && (lens32[7] == 0);
    if (is64) return (int)((const long long*)lens32)[b];
    return lens32[b];
}

// shared 8x8 f32x2 outer-product step
__device__ __forceinline__ void mma_step(const float* __restrict__ asrow,
                                         const float* __restrict__ bsrow,
                                         int ty8, int tx8,
                                         unsigned long long acc[8][4]) {
    float4 a0 = *(const float4*)(asrow + ty8);
    float4 a1 = *(const float4*)(asrow + ty8 + 4);
    unsigned long long a[8] = {fdup(a0.x), fdup(a0.y), fdup(a0.z), fdup(a0.w),
                               fdup(a1.x), fdup(a1.y), fdup(a1.z), fdup(a1.w)};
    const unsigned long long* bp = (const unsigned long long*)(bsrow + tx8);
    unsigned long long b0 = bp[0], b1 = bp[1], b2 = bp[2], b3 = bp[3];
#pragma unroll
    for (int i = 0; i < 8; ++i) {
        ffma2(acc[i][0], a[i], b0);
        ffma2(acc[i][1], a[i], b1);
        ffma2(acc[i][2], a[i], b2);
        ffma2(acc[i][3], a[i], b3);
    }
}

// ---------------- init ----------------
__global__ void k_init() {
    int i = blockIdx.x * blockDim.x + threadIdx.x;
    if (i < BB * TT) g_rowmax[i] = 0x007FFFFFu;  // fenc(-inf)
}

// ---------------- GEMM1: align = source @ memory_bank^T, mask, rowmax ----------------
__global__ void __launch_bounds__(256) k_gemm1(const float* __restrict__ src,
                                               const float* __restrict__ mb,
                                               const int* __restrict__ lens32) {
    __shared__ __align__(16) float As[2][16][132];
    __shared__ __align__(16) float Bs[2][16][132];
    __shared__ float red[128][17];

    const int tid = threadIdx.x;
    const int tx = tid & 15, ty = tid >> 4;
    const int bz = blockIdx.z;
    const int t0 = blockIdx.y * 128;
    const int s0 = blockIdx.x * 128;

    const float* A  = src + (size_t)bz * TT * DD;
    const float* Bm = mb  + (size_t)bz * SS * DD;

    const int row0 = tid >> 2;           // 0..63
    const int c4   = (tid & 3) * 4;      // 0,4,8,12

    float4 pa[2], pb[2];
#pragma unroll
    for (int l = 0; l < 2; ++l) {
        int row = row0 + l * 64;
        pa[l] = *(const float4*)(A  + (size_t)(t0 + row) * DD + c4);
        pb[l] = *(const float4*)(Bm + (size_t)(s0 + row) * DD + c4);
    }
#pragma unroll
    for (int l = 0; l < 2; ++l) {
        int row = row0 + l * 64;
        As[0][c4 + 0][row] = pa[l].x; As[0][c4 + 1][row] = pa[l].y;
        As[0][c4 + 2][row] = pa[l].z; As[0][c4 + 3][row] = pa[l].w;
        Bs[0][c4 + 0][row] = pb[l].x; Bs[0][c4 + 1][row] = pb[l].y;
        Bs[0][c4 + 2][row] = pb[l].z; Bs[0][c4 + 3][row] = pb[l].w;
    }
    __syncthreads();

    unsigned long long acc[8][4];
#pragma unroll
    for (int i = 0; i < 8; ++i)
#pragma unroll
        for (int j = 0; j < 4; ++j) acc[i][j] = 0ull;

    for (int kt = 0; kt < 16; ++kt) {
        int buf = kt & 1;
        if (kt < 15) {
            int k0 = (kt + 1) * 16;
#pragma unroll
            for (int l = 0; l < 2; ++l) {
                int row = row0 + l * 64;
                pa[l] = *(const float4*)(A  + (size_t)(t0 + row) * DD + k0 + c4);
                pb[l] = *(const float4*)(Bm + (size_t)(s0 + row) * DD + k0 + c4);
            }
        }
#pragma unroll
        for (int k = 0; k < 16; ++k)
            mma_step(&As[buf][k][0], &Bs[buf][k][0], ty * 8, tx * 8, acc);
        if (kt < 15) {
            int nb = buf ^ 1;
#pragma unroll
            for (int l = 0; l < 2; ++l) {
                int row = row0 + l * 64;
                As[nb][c4 + 0][row] = pa[l].x; As[nb][c4 + 1][row] = pa[l].y;
                As[nb][c4 + 2][row] = pa[l].z; As[nb][c4 + 3][row] = pa[l].w;
                Bs[nb][c4 + 0][row] = pb[l].x; Bs[nb][c4 + 1][row] = pb[l].y;
                Bs[nb][c4 + 2][row] = pb[l].z; Bs[nb][c4 + 3][row] = pb[l].w;
            }
        }
        __syncthreads();
    }

    const int len = decode_len(lens32, bz);
#pragma unroll
    for (int i = 0; i < 8; ++i) {
        int t  = t0 + ty * 8 + i;
        int sb = s0 + tx * 8;
        float v[8];
#pragma unroll
        for (int j = 0; j < 4; ++j) { v[2 * j] = lo32(acc[i][j]); v[2 * j + 1] = hi32(acc[i][j]); }
        float m = -INFINITY;
#pragma unroll
        for (int jj = 0; jj < 8; ++jj) {
            if (sb + jj >= len) v[jj] = -INFINITY;
            m = fmaxf(m, v[jj]);
        }
        float4* op = (float4*)(g_align + (size_t)(bz * TT + t) * SS + sb);
        op[0] = make_float4(v[0], v[1], v[2], v[3]);
        op[1] = make_float4(v[4], v[5], v[6], v[7]);
        red[ty * 8 + i][tx] = m;
    }
    __syncthreads();
    if (tid < 128) {
        float m = red[tid][0];
#pragma unroll
        for (int j = 1; j < 16; ++j) m = fmaxf(m, red[tid][j]);
        atomicMax(&g_rowmax[bz * TT + t0 + tid], fenc(m));
    }
}

// ---------------- Phase A: per-chunk column sums of exp (no exp store) ----------------
__global__ void __launch_bounds__(256) k_colsum() {
    const int b  = blockIdx.z;
    const int ch = blockIdx.y;
    const int s  = blockIdx.x * 256 + threadIdx.x;
    __shared__ float mrow[TCH];
    if (threadIdx.x < TCH) mrow[threadIdx.x] = fdec(g_rowmax[b * TT + ch * TCH + threadIdx.x]);
    __syncthreads();
    size_t base = (size_t)(b * TT + ch * TCH) * SS + s;
    float sum = 0.f;
#pragma unroll 4
    for (int r = 0; r < TCH; ++r)
        sum += expf(g_align[base + (size_t)r * SS] - mrow[r]);
    g_carry[(b * NCHUNK + ch) * SS + s] = sum;
}

// ---------------- tiny exclusive scan over chunks ----------------
__global__ void k_scan() {
    int i = blockIdx.x * blockDim.x + threadIdx.x;
    if (i >= BB * SS) return;
    int b = i / SS, s = i % SS;
    float run = 0.f;
    for (int c = 0; c < NCHUNK; ++c) {
        int idx = (b * NCHUNK + c) * SS + s;
        float v = g_carry[idx];
        g_carry[idx] = run;
        run += v;
    }
}

// ---------------- Phase C: recompute exp, u in place, partial rowsums ----------------
__global__ void __launch_bounds__(256) k_phasec() {
    const int b  = blockIdx.z;
    const int ch = blockIdx.y;
    const int s  = blockIdx.x * 256 + threadIdx.x;
    const int lane = threadIdx.x & 31;
    const int warp = threadIdx.x >> 5;
    __shared__ float mrow[TCH];
    if (threadIdx.x < TCH) mrow[threadIdx.x] = fdec(g_rowmax[b * TT + ch * TCH + threadIdx.x]);
    __syncthreads();

    float P = g_carry[(b * NCHUNK + ch) * SS + s];
    size_t base = (size_t)(b * TT + ch * TCH) * SS + s;
#pragma unroll 2
    for (int r = 0; r < TCH; ++r) {
        int t = ch * TCH + r;
        size_t off = base + (size_t)r * SS;
        float e = expf(g_align[off] - mrow[r]);
        float pen = (t == 0) ? 1.0f : P;
        float u = e / (pen + 1e-20f);
        P += e;
        g_align[off] = u;          // unnormalized weight, in place
        float w = u;
        w += __shfl_down_sync(0xffffffffu, w, 16);
        w += __shfl_down_sync(0xffffffffu, w, 8);
        w += __shfl_down_sync(0xffffffffu, w, 4);
        w += __shfl_down_sync(0xffffffffu, w, 2);
        w += __shfl_down_sync(0xffffffffu, w, 1);
        if (lane == 0) g_partial[(size_t)(b * TT + t) * 64 + blockIdx.x * 8 + warp] = w;
    }
}

// ---------------- deterministic rowsum reduce -> inverse ----------------
__global__ void k_rowsum() {
    int i = blockIdx.x * blockDim.x + threadIdx.x;
    if (i >= BB * TT) return;
    const float* p = g_partial + (size_t)i * 64;
    float s = 0.f;
#pragma unroll
    for (int j = 0; j < 64; ++j) s += p[j];
    g_invsum[i] = 1.0f / s;
}

// ---------------- write normalized align_vectors to d_out ----------------
__global__ void __launch_bounds__(256) k_norm(float* __restrict__ av) {
    int row = blockIdx.x;
    float inv = g_invsum[row];
    const float4* up = (const float4*)(g_align + (size_t)row * SS);
    float4* op = (float4*)(av + (size_t)row * SS);
    int t = threadIdx.x;
    float4 a = up[t];
    a.x *= inv; a.y *= inv; a.z *= inv; a.w *= inv;
    op[t] = a;
    float4 c = up[t + 256];
    c.x *= inv; c.y *= inv; c.z *= inv; c.w *= inv;
    op[t + 256] = c;
}

// ---------------- GEMM2: c = (u @ memory_bank) * invsum ----------------
__global__ void __launch_bounds__(256) k_gemm2(const float* __restrict__ mb) {
    __shared__ __align__(16) float As[2][16][132];
    __shared__ __align__(16) float Bs[2][16][132];

    const int tid = threadIdx.x;
    const int tx = tid & 15, ty = tid >> 4;
    const int bz = blockIdx.z;
    const int t0 = blockIdx.y * 128;
    const int n0 = blockIdx.x * 128;

    const float* A  = g_align + (size_t)bz * TT * SS;
    const float* Bm = mb      + (size_t)bz * SS * DD;

    const int row0 = tid >> 2;
    const int c4   = (tid & 3) * 4;
    const int r2_0 = tid >> 5;           // 0..7
    const int c2   = (tid & 31) * 4;     // 0..124

    float4 pa[2], pb[2];
#pragma unroll
    for (int l = 0; l < 2; ++l) {
        int row = row0 + l * 64;
        pa[l] = *(const float4*)(A + (size_t)(t0 + row) * SS + c4);
        int r2 = r2_0 + l * 8;
        pb[l] = *(const float4*)(Bm + (size_t)r2 * DD + n0 + c2);
    }
#pragma unroll
    for (int l = 0; l < 2; ++l) {
        int row = row0 + l * 64;
        As[0][c4 + 0][row] = pa[l].x; As[0][c4 + 1][row] = pa[l].y;
        As[0][c4 + 2][row] = pa[l].z; As[0][c4 + 3][row] = pa[l].w;
        int r2 = r2_0 + l * 8;
        *(float4*)&Bs[0][r2][c2] = pb[l];
    }
    __syncthreads();

    unsigned long long acc[8][4];
#pragma unroll
    for (int i = 0; i < 8; ++i)
#pragma unroll
        for (int j = 0; j < 4; ++j) acc[i][j] = 0ull;

    for (int kt = 0; kt < SS / 16; ++kt) {
        int buf = kt & 1;
        if (kt < SS / 16 - 1) {
            int k0 = (kt + 1) * 16;
#pragma unroll
            for (int l = 0; l < 2; ++l) {
                int row = row0 + l * 64;
                pa[l] = *(const float4*)(A + (size_t)(t0 + row) * SS + k0 + c4);
                int r2 = r2_0 + l * 8;
                pb[l] = *(const float4*)(Bm + (size_t)(k0 + r2) * DD + n0 + c2);
            }
        }
#pragma unroll
        for (int k = 0; k < 16; ++k)
            mma_step(&As[buf][k][0], &Bs[buf][k][0], ty * 8, tx * 8, acc);
        if (kt < SS / 16 - 1) {
            int nb = buf ^ 1;
#pragma unroll
            for (int l = 0; l < 2; ++l) {
                int row = row0 + l * 64;
                As[nb][c4 + 0][row] = pa[l].x; As[nb][c4 + 1][row] = pa[l].y;
                As[nb][c4 + 2][row] = pa[l].z; As[nb][c4 + 3][row] = pa[l].w;
                int r2 = r2_0 + l * 8;
                *(float4*)&Bs[nb][r2][c2] = pb[l];
            }
        }
        __syncthreads();
    }

#pragma unroll
    for (int i = 0; i < 8; ++i) {
        int t = t0 + ty * 8 + i;
        float inv = g_invsum[bz * TT + t];
        float v[8];
#pragma unroll
        for (int j = 0; j < 4; ++j) { v[2 * j] = lo32(acc[i][j]); v[2 * j + 1] = hi32(acc[i][j]); }
#pragma unroll
        for (int jj = 0; jj < 8; ++jj) v[jj] *= inv;
        float4* op = (float4*)(g_c + (size_t)(bz * TT + t) * DD + n0 + tx * 8);
        op[0] = make_float4(v[0], v[1], v[2], v[3]);
        op[1] = make_float4(v[4], v[5], v[6], v[7]);
    }
}

// ---------------- GEMM3: attn_h = tanh([c, source] @ W_out) ----------------
__global__ void __launch_bounds__(256) k_gemm3(const float* __restrict__ src,
                                               const float* __restrict__ W,
                                               float* __restrict__ outh) {
    __shared__ __align__(16) float As[2][16][132];
    __shared__ __align__(16) float Bs[2][16][132];

    const int tid = threadIdx.x;
    const int tx = tid & 15, ty = tid >> 4;
    const int m0 = blockIdx.y * 128;
    const int n0 = blockIdx.x * 128;

    const int row0 = tid >> 2;
    const int c4   = (tid & 3) * 4;
    const int r2_0 = tid >> 5;
    const int c2   = (tid & 31) * 4;

    float4 pa[2], pb[2];
#pragma unroll
    for (int l = 0; l < 2; ++l) {
        int row = row0 + l * 64;
        int m = m0 + row;
        pa[l] = *(const float4*)(g_c + (size_t)m * DD + c4);
        int r2 = r2_0 + l * 8;
        pb[l] = *(const float4*)(W + (size_t)r2 * DD + n0 + c2);
    }
#pragma unroll
    for (int l = 0; l < 2; ++l) {
        int row = row0 + l * 64;
        As[0][c4 + 0][row] = pa[l].x; As[0][c4 + 1][row] = pa[l].y;
        As[0][c4 + 2][row] = pa[l].z; As[0][c4 + 3][row] = pa[l].w;
        int r2 = r2_0 + l * 8;
        *(float4*)&Bs[0][r2][c2] = pb[l];
    }
    __syncthreads();

    unsigned long long acc[8][4];
#pragma unroll
    for (int i = 0; i < 8; ++i)
#pragma unroll
        for (int j = 0; j < 4; ++j) acc[i][j] = 0ull;

    for (int kt = 0; kt < (2 * DD) / 16; ++kt) {
        int buf = kt & 1;
        if (kt < (2 * DD) / 16 - 1) {
            int k0 = (kt + 1) * 16;
#pragma unroll
            for (int l = 0; l < 2; ++l) {
                int row = row0 + l * 64;
                int m = m0 + row;
                int kg = k0 + c4;
                const float* ap = (kg < DD) ? (g_c + (size_t)m * DD + kg)
                                            : (src + (size_t)m * DD + (kg - DD));
                pa[l] = *(const float4*)ap;
                int r2 = r2_0 + l * 8;
                pb[l] = *(const float4*)(W + (size_t)(k0 + r2) * DD + n0 + c2);
            }
        }
#pragma unroll
        for (int k = 0; k < 16; ++k)
            mma_step(&As[buf][k][0], &Bs[buf][k][0], ty * 8, tx * 8, acc);
        if (kt < (2 * DD) / 16 - 1) {
            int nb = buf ^ 1;
#pragma unroll
            for (int l = 0; l < 2; ++l) {
                int row = row0 + l * 64;
                As[nb][c4 + 0][row] = pa[l].x; As[nb][c4 + 1][row] = pa[l].y;
                As[nb][c4 + 2][row] = pa[l].z; As[nb][c4 + 3][row] = pa[l].w;
                int r2 = r2_0 + l * 8;
                *(float4*)&Bs[nb][r2][c2] = pb[l];
            }
        }
        __syncthreads();
    }

#pragma unroll
    for (int i = 0; i < 8; ++i) {
        int m = m0 + ty * 8 + i;
        float v[8];
#pragma unroll
        for (int j = 0; j < 4; ++j) { v[2 * j] = lo32(acc[i][j]); v[2 * j + 1] = hi32(acc[i][j]); }
#pragma unroll
        for (int jj = 0; jj < 8; ++jj) v[jj] = tanhf(v[jj]);
        float4* op = (float4*)(outh + (size_t)m * DD + n0 + tx * 8);
        op[0] = make_float4(v[0], v[1], v[2], v[3]);
        op[1] = make_float4(v[4], v[5], v[6], v[7]);
    }
}

// ---------------- launch ----------------
extern "C" void kernel_launch(void* const* d_in, const int* in_sizes, int n_in,
                              void* d_out, int out_size) {
    const float* src  = (const float*)d_in[0];      // [B,T,D]
    const float* mb   = (const float*)d_in[1];      // [B,S,D]
    const float* W    = (const float*)d_in[2];      // [2D,D]
    const int*   lens = (const int*)d_in[3];        // [B] (int32 or int64; decoded in-kernel)

    float* outh = (float*)d_out;                    // attn_h   [B,T,D]
    float* av   = outh + (size_t)BB * TT * DD;      // align_vectors [B,T,S]

    k_init<<<(BB * TT + 255) / 256, 256>>>();
    k_gemm1<<<dim3(SS / 128, TT / 128, BB), 256>>>(src, mb, lens);
    k_colsum<<<dim3(SS / 256, NCHUNK, BB), 256>>>();
    k_scan<<<(BB * SS + 255) / 256, 256>>>();
    k_phasec<<<dim3(SS / 256, NCHUNK, BB), 256>>>();
    k_rowsum<<<(BB * TT + 255) / 256, 256>>>();
    k_norm<<<BB * TT, 256>>>(av);
    k_gemm2<<<dim3(DD / 128, TT / 128, BB), 256>>>(mb);
    k_gemm3<<<dim3(DD / 128, (BB * TT) / 128, 1), 256>>>(src, W, outh);
}